// round 17
// baseline (speedup 1.0000x reference)
#include <cuda_runtime.h>
#include <cuda_fp16.h>
#include <math.h>

#define EMB 64
#define RNN 128
#define BB  512
#define LL  256
#define KK  18
#define G   8
#define ZC  512   // 4*RNN
#define VOCAB 30001
#define PBR 32    // vocab rows per pbuild block
#define LB  64    // (b,t) rows per logits block
#define HSP 264   // padded half-row (2*RNN + 8) to avoid qr bank conflicts

// Scratch (static device allocations; no cudaMalloc allowed)
__device__ uint2 g_P2[2][VOCAB][RNN];                 // ~61 MB (L2-resident)
__device__ unsigned int g_hstage[2][BB / G][LL][512]; // coalesced writes
__device__ float g_logits[BB][LL][KK];

typedef unsigned long long u64;
typedef unsigned int u32;

__device__ __forceinline__ float fast_tanh(float x) {
    float y; asm("tanh.approx.f32 %0, %1;" : "=f"(y) : "f"(x)); return y;
}
__device__ __forceinline__ u32 pack_h2(float lo, float hi) {
    __half2 v = __floats2half2_rn(lo, hi);
    return *(u32*)&v;
}
__device__ __forceinline__ float2 unpack_h2(u32 v) {
    return __half22float2(*(__half2*)&v);
}
__device__ __forceinline__ __half2 h2_of(u32 v) { return *(__half2*)&v; }
__device__ __forceinline__ u32 u_of(__half2 v) { return *(u32*)&v; }
__device__ __forceinline__ __half2 h2tanh_a(__half2 x) {
    u32 y; asm("tanh.approx.f16x2 %0, %1;" : "=r"(y) : "r"(u_of(x)));
    return h2_of(y);
}
__device__ __forceinline__ __half2 h2sig_a(__half2 x) {
    // sig(x) = 0.5*tanh(0.5x) + 0.5, packed
    __half2 h05 = __floats2half2_rn(0.5f, 0.5f);
    return __hfma2(h2tanh_a(__hmul2(x, h05)), h05, h05);
}

// m16n8k16 fp16 in / fp16 accumulate
__device__ __forceinline__ void mma16816h(u32& c0, u32& c1,
                                          u32 a0, u32 a1, u32 a2, u32 a3,
                                          u32 b0, u32 b1) {
    asm("mma.sync.aligned.m16n8k16.row.col.f16.f16.f16.f16 "
        "{%0,%1}, {%2,%3,%4,%5}, {%6,%7}, {%0,%1};"
        : "+r"(c0), "+r"(c1)
        : "r"(a0), "r"(a1), "r"(a2), "r"(a3), "r"(b0), "r"(b1));
}
// m16n8k16 fp16 in / fp32 accumulate (logits)
__device__ __forceinline__ void mma16816f(float& d0, float& d1, float& d2, float& d3,
                                          u32 a0, u32 a1, u32 a2, u32 a3,
                                          u32 b0, u32 b1) {
    asm("mma.sync.aligned.m16n8k16.row.col.f32.f16.f16.f32 "
        "{%0,%1,%2,%3}, {%4,%5,%6,%7}, {%8,%9}, {%0,%1,%2,%3};"
        : "+f"(d0), "+f"(d1), "+f"(d2), "+f"(d3)
        : "r"(a0), "r"(a1), "r"(a2), "r"(a3), "r"(b0), "r"(b1));
}

// ---------------------------------------------------------------------------
// Kernel 1: P2 via fp16 HMMA (unchanged winning version)
// ---------------------------------------------------------------------------
__global__ __launch_bounds__(256) void pbuild_kernel(
    const float* __restrict__ E,
    const float* __restrict__ Wx_f, const float* __restrict__ b_f,
    const float* __restrict__ Wx_b, const float* __restrict__ b_b)
{
    int dir = blockIdx.y;
    int r0  = blockIdx.x * PBR;
    const float* __restrict__ Wx = dir ? Wx_b : Wx_f;
    const float* __restrict__ bs = dir ? b_b : b_f;

    __shared__ __half es[PBR][EMB];
    __shared__ u32 zs[PBR][ZC / 2];

    int tid  = threadIdx.x;
    int w    = tid >> 5;
    int lane = tid & 31;
    int qr   = lane >> 2;
    int tl   = lane & 3;

    for (int i = tid; i < PBR * EMB; i += 256) {
        int r = i >> 6, e = i & 63;
        int row = r0 + r;
        int rc = (row < VOCAB) ? row : (VOCAB - 1);
        es[r][e] = __float2half(E[rc * EMB + e]);
    }

    u32 bfr[8][4][2];
#pragma unroll
    for (int nt = 0; nt < 8; nt++) {
        int n = 64 * w + 8 * nt + qr;
#pragma unroll
        for (int kt = 0; kt < 4; kt++) {
            int k0 = 16 * kt + 2 * tl;
            bfr[nt][kt][0] = pack_h2(Wx[k0 * ZC + n],       Wx[(k0 + 1) * ZC + n]);
            bfr[nt][kt][1] = pack_h2(Wx[(k0 + 8) * ZC + n], Wx[(k0 + 9) * ZC + n]);
        }
    }
    u32 binit[8];
#pragma unroll
    for (int nt = 0; nt < 8; nt++) {
        int c = 64 * w + 8 * nt + 2 * tl;
        binit[nt] = pack_h2(bs[c], bs[c + 1]);
    }
    __syncthreads();

#pragma unroll
    for (int mt = 0; mt < 2; mt++) {
        int rb = 16 * mt;
        u32 a[4][4];
#pragma unroll
        for (int kt = 0; kt < 4; kt++) {
            int k0 = 16 * kt + 2 * tl;
            a[kt][0] = *(const u32*)&es[rb + qr][k0];
            a[kt][1] = *(const u32*)&es[rb + 8 + qr][k0];
            a[kt][2] = *(const u32*)&es[rb + qr][k0 + 8];
            a[kt][3] = *(const u32*)&es[rb + 8 + qr][k0 + 8];
        }
#pragma unroll
        for (int nt = 0; nt < 8; nt++) {
            u32 c0 = binit[nt], c1 = binit[nt];
#pragma unroll
            for (int kt = 0; kt < 4; kt++)
                mma16816h(c0, c1, a[kt][0], a[kt][1], a[kt][2], a[kt][3],
                          bfr[nt][kt][0], bfr[nt][kt][1]);
            int cp = 32 * w + 4 * nt + tl;
            zs[rb + qr][cp]     = c0;
            zs[rb + 8 + qr][cp] = c1;
        }
    }
    __syncthreads();

    const __half* zh = (const __half*)zs;
    for (int i = tid; i < PBR * RNN; i += 256) {
        int r = i >> 7, u = i & 127;
        int row = r0 + r;
        if (row < VOCAB) {
            const __half* zr = zh + r * ZC;
            g_P2[dir][row][u] = make_uint2(
                u_of(__halves2half2(zr[u],       zr[u + 128])),
                u_of(__halves2half2(zr[u + 256], zr[u + 384])));
        }
    }
}

// ---------------------------------------------------------------------------
// Kernel 2: persistent LSTM (fp16 HMMA, FULLY packed half2 epilogue; c in fp16)
// ---------------------------------------------------------------------------
__global__ __launch_bounds__(512, 1) void lstm_kernel(
    const int* __restrict__ inputs,
    const float* __restrict__ Wh_f, const float* __restrict__ Wh_b)
{
    __shared__ __align__(16) u32 hA[512];
    __shared__ __align__(16) u32 hB[512];
    __shared__ __align__(8) int2 tok2_s[LL][4];

    int dir = blockIdx.x >> 6;
    int bi  = blockIdx.x & 63;
    int b0  = bi * G;
    const float* __restrict__ Wh = dir ? Wh_b : Wh_f;
    int tid  = threadIdx.x;
    int w    = tid >> 5;
    int lane = tid & 31;
    int gm   = lane >> 2;
    int tl   = lane & 3;

    for (int i = tid; i < 512; i += 512) { hA[i] = 0u; hB[i] = 0u; }
    for (int i = tid; i < 4 * LL; i += 512) {
        int t = i >> 2, pr = i & 3;
        tok2_s[t][pr] = make_int2(inputs[(b0 + 2 * pr) * LL + t],
                                  inputs[(b0 + 2 * pr + 1) * LL + t]);
    }

    int u = 8 * w + gm;

    u32 afr[2][8][4];
#pragma unroll
    for (int ti = 0; ti < 2; ti++) {
        int oA = (2 * ti) * 128 + u;
        int oB = oA + 128;
#pragma unroll
        for (int kc = 0; kc < 8; kc++) {
            int kb = 16 * kc + 2 * tl;
            afr[ti][kc][0] = pack_h2(Wh[kb * ZC + oA],       Wh[(kb + 1) * ZC + oA]);
            afr[ti][kc][1] = pack_h2(Wh[kb * ZC + oB],       Wh[(kb + 1) * ZC + oB]);
            afr[ti][kc][2] = pack_h2(Wh[(kb + 8) * ZC + oA], Wh[(kb + 9) * ZC + oA]);
            afr[ti][kc][3] = pack_h2(Wh[(kb + 8) * ZC + oB], Wh[(kb + 9) * ZC + oB]);
        }
    }
    __syncthreads();

    int be = 2 * tl;
    int j = u & 15, kch = u >> 4;
    int rr = (j >> 3) & 1, tlp = (j & 7) >> 1, half = j & 1;
    int hwE = ((kch * 64 + (be * 4 + tlp) * 2 + rr) << 1) + half;
    int hwO = hwE + 16;

    u32* stage = &g_hstage[dir][bi][0][0];

    int t0 = dir ? (LL - 1) : 0;
    int2 tk = tok2_s[t0][tl];
    uint2 pE = g_P2[dir][tk.x][u];
    uint2 pO = g_P2[dir][tk.y][u];

    __half2 c_h2 = __floats2half2_rn(0.0f, 0.0f);

    for (int step = 0; step < LL; step++) {
        int t = dir ? (LL - 1 - step) : step;
        const u32* rd = (step & 1) ? hB : hA;
        __half* wrh = (__half*)((step & 1) ? hA : hB);

        u32 cA[2][2], cB[2][2];
        {
            __half2 eif = h2_of(pE.x), oif = h2_of(pO.x);
            __half2 ego = h2_of(pE.y), ogo = h2_of(pO.y);
            cA[0][0] = u_of(__lows2half2(eif, oif));
            cA[0][1] = u_of(__highs2half2(eif, oif));
            cA[1][0] = u_of(__lows2half2(ego, ogo));
            cA[1][1] = u_of(__highs2half2(ego, ogo));
            cB[0][0] = cB[0][1] = cB[1][0] = cB[1][1] = 0u;
        }

        int tn = (step + 1 < LL) ? (dir ? t - 1 : t + 1) : t;
        tk = tok2_s[tn][tl];
        pE = g_P2[dir][tk.x][u];
        pO = g_P2[dir][tk.y][u];

#pragma unroll
        for (int kc = 0; kc < 4; kc++) {
            uint2 bb = *(const uint2*)&rd[kc * 64 + lane * 2];
            mma16816h(cA[0][0], cA[0][1],
                      afr[0][kc][0], afr[0][kc][1], afr[0][kc][2], afr[0][kc][3],
                      bb.x, bb.y);
            mma16816h(cA[1][0], cA[1][1],
                      afr[1][kc][0], afr[1][kc][1], afr[1][kc][2], afr[1][kc][3],
                      bb.x, bb.y);
            uint2 bb2 = *(const uint2*)&rd[(kc + 4) * 64 + lane * 2];
            mma16816h(cB[0][0], cB[0][1],
                      afr[0][kc + 4][0], afr[0][kc + 4][1], afr[0][kc + 4][2], afr[0][kc + 4][3],
                      bb2.x, bb2.y);
            mma16816h(cB[1][0], cB[1][1],
                      afr[1][kc + 4][0], afr[1][kc + 4][1], afr[1][kc + 4][2], afr[1][kc + 4][3],
                      bb2.x, bb2.y);
        }

        // fully packed epilogue: (E,O) pairs in half2 end-to-end
        __half2 si = h2sig_a (__hadd2(h2_of(cA[0][0]), h2_of(cB[0][0])));
        __half2 sf = h2sig_a (__hadd2(h2_of(cA[0][1]), h2_of(cB[0][1])));
        __half2 tg = h2tanh_a(__hadd2(h2_of(cA[1][0]), h2_of(cB[1][0])));
        __half2 so = h2sig_a (__hadd2(h2_of(cA[1][1]), h2_of(cB[1][1])));

        c_h2 = __hfma2(sf, c_h2, __hmul2(si, tg));
        __half2 h2v = __hmul2(so, h2tanh_a(c_h2));

        wrh[hwE] = __low2half(h2v);
        wrh[hwO] = __high2half(h2v);
        stage[t * 512 + tid] = u_of(h2v);
        __syncthreads();
    }
}

// ---------------------------------------------------------------------------
// Kernel 3: logits via fp16 HMMA, fp32 accumulate (unchanged winning version)
// ---------------------------------------------------------------------------
__global__ __launch_bounds__(128) void logits_kernel(
    const float* __restrict__ Wd, const float* __restrict__ bd)
{
    __shared__ __half hs[LB][HSP];
    __shared__ __half wdt[24][HSP];
    __shared__ float bd_s[24];

    int tid  = threadIdx.x;
    int w    = tid >> 5;
    int lane = tid & 31;
    int qr   = lane >> 2;
    int tl   = lane & 3;
    int bt0  = blockIdx.x * LB;

    for (int i = tid; i < 24 * 256; i += 128) {
        int n = i >> 8, kx = i & 255;
        wdt[n][kx] = (n < KK) ? __float2half(Wd[kx * KK + n]) : __ushort_as_half(0);
    }
    if (tid < 24) bd_s[tid] = (tid < KK) ? bd[tid] : 0.0f;

    for (int i = tid; i < LB * 256; i += 128) {
        int r = i >> 8, e = i & 255;
        int bt = bt0 + r;
        int b = bt >> 8, t = bt & 255;
        int dir = e >> 7, uu = e & 127;
        u32 v = g_hstage[dir][b >> 3][t][(uu >> 3) * 32 + (uu & 7) * 4 + ((b & 7) >> 1)];
        __half2 hh = h2_of(v);
        hs[r][e] = (b & 1) ? __high2half(hh) : __low2half(hh);
    }
    __syncthreads();

    int r0w = w * 16;

    u32 bfr[3][16][2];
#pragma unroll
    for (int nt = 0; nt < 3; nt++) {
        int n = 8 * nt + qr;
#pragma unroll
        for (int kt = 0; kt < 16; kt++) {
            int k0 = 16 * kt + 2 * tl;
            bfr[nt][kt][0] = *(const u32*)&wdt[n][k0];
            bfr[nt][kt][1] = *(const u32*)&wdt[n][k0 + 8];
        }
    }

    float d[3][4];
#pragma unroll
    for (int nt = 0; nt < 3; nt++) {
        float blo = bd_s[8 * nt + 2 * tl], bhi = bd_s[8 * nt + 2 * tl + 1];
        d[nt][0] = blo; d[nt][1] = bhi; d[nt][2] = blo; d[nt][3] = bhi;
    }

#pragma unroll
    for (int kt = 0; kt < 16; kt++) {
        int k0 = 16 * kt + 2 * tl;
        u32 a0 = *(const u32*)&hs[r0w + qr][k0];
        u32 a1 = *(const u32*)&hs[r0w + 8 + qr][k0];
        u32 a2 = *(const u32*)&hs[r0w + qr][k0 + 8];
        u32 a3 = *(const u32*)&hs[r0w + 8 + qr][k0 + 8];
#pragma unroll
        for (int nt = 0; nt < 3; nt++)
            mma16816f(d[nt][0], d[nt][1], d[nt][2], d[nt][3],
                      a0, a1, a2, a3, bfr[nt][kt][0], bfr[nt][kt][1]);
    }

    int btA = bt0 + r0w + qr, btB = btA + 8;
    int bA = btA >> 8, tA = btA & 255;
    int bBv = btB >> 8, tB = btB & 255;
#pragma unroll
    for (int nt = 0; nt < 3; nt++) {
        int kc = 8 * nt + 2 * tl;
        if (kc < KK) {
            g_logits[bA][tA][kc]  = d[nt][0];
            g_logits[bBv][tB][kc] = d[nt][2];
        }
        if (kc + 1 < KK) {
            g_logits[bA][tA][kc + 1]  = d[nt][1];
            g_logits[bBv][tB][kc + 1] = d[nt][3];
        }
    }
}

// ---------------------------------------------------------------------------
// Kernel 4: CRF (proven shape). expT column held in REGISTERS (no LDS in the
// serial scan). Tree-split sum, prefetch depth 2.
// ---------------------------------------------------------------------------
__global__ __launch_bounds__(128) void crf_kernel(
    const int* __restrict__ labels, const float* __restrict__ T,
    float* __restrict__ out, int out_size)
{
    if (blockIdx.x == BB / 4) {
        for (int i = threadIdx.x; i < KK * KK; i += 128)
            if ((BB + i) < out_size) out[BB + i] = T[i];
        return;
    }

    __shared__ float T_s[KK * KK];
    int tid = threadIdx.x;
    for (int i = tid; i < KK * KK; i += 128) T_s[i] = T[i];
    __syncthreads();

    int warp = tid >> 5;
    int lane = tid & 31;
    int b = blockIdx.x * 4 + warp;
    if (b >= BB) return;

    int k = (lane < KK) ? lane : 0;
    // expT column k in registers
    float rT[KK];
#pragma unroll
    for (int k1 = 0; k1 < KK; k1++) rT[k1] = __expf(T_s[k1 * KK + k]);

    const int* lab = labels + b * LL;

    int cnt = 0;
    for (int l = lane; l < LL; l += 32) cnt += (lab[l] != 0);
#pragma unroll
    for (int off = 16; off; off >>= 1) cnt += __shfl_xor_sync(0xffffffffu, cnt, off);
    int len = cnt;

    float us = 0.0f, bs = 0.0f;
    for (int l = lane; l < LL; l += 32) {
        int y = lab[l];
        if (l < len) us += g_logits[b][l][y];
        if (l >= 1 && l < len) bs += T_s[lab[l - 1] * KK + y];
    }
#pragma unroll
    for (int off = 16; off; off >>= 1) {
        us += __shfl_xor_sync(0xffffffffu, us, off);
        bs += __shfl_xor_sync(0xffffffffu, bs, off);
    }

    float alpha = (lane < KK) ? g_logits[b][0][k] : -1e30f;
    float lg0 = g_logits[b][1][k];
    float lg1 = g_logits[b][2][k];
    for (int l = 1; l < LL; l++) {
        float lgn = (l + 2 < LL) ? g_logits[b][l + 2][k] : 0.0f;
        float a0 = __shfl_sync(0xffffffffu, alpha, 0);
        float e = (lane < KK) ? __expf(alpha - a0) : 0.0f;
        float s0 = 0.f, s1 = 0.f, s2 = 0.f;
#pragma unroll
        for (int k1 = 0; k1 < 6; k1++) {
            s0 = fmaf(__shfl_sync(0xffffffffu, e, k1),      rT[k1],      s0);
            s1 = fmaf(__shfl_sync(0xffffffffu, e, k1 + 6),  rT[k1 + 6],  s1);
            s2 = fmaf(__shfl_sync(0xffffffffu, e, k1 + 12), rT[k1 + 12], s2);
        }
        float na = a0 + __logf((s0 + s1) + s2) + lg0;
        if (lane < KK && l < len) alpha = na;
        lg0 = lg1;
        lg1 = lgn;
    }

    float m = alpha;
#pragma unroll
    for (int off = 16; off; off >>= 1) m = fmaxf(m, __shfl_xor_sync(0xffffffffu, m, off));
    float es = (lane < KK) ? __expf(alpha - m) : 0.0f;
#pragma unroll
    for (int off = 16; off; off >>= 1) es += __shfl_xor_sync(0xffffffffu, es, off);
    float lse = m + __logf(es);

    if (lane == 0 && b < out_size) out[b] = us + bs - lse;
}

// ---------------------------------------------------------------------------
extern "C" void kernel_launch(void* const* d_in, const int* in_sizes, int n_in,
                              void* d_out, int out_size)
{
    const int*   inputs = (const int*)  d_in[0];
    const int*   labels = (const int*)  d_in[1];
    const float* E      = (const float*)d_in[2];
    const float* Wx_f   = (const float*)d_in[3];
    const float* Wh_f   = (const float*)d_in[4];
    const float* b_f    = (const float*)d_in[5];
    const float* Wx_b   = (const float*)d_in[6];
    const float* Wh_b   = (const float*)d_in[7];
    const float* b_b    = (const float*)d_in[8];
    const float* Wd     = (const float*)d_in[9];
    const float* bd     = (const float*)d_in[10];
    const float* T      = (const float*)d_in[11];
    float* out = (float*)d_out;

    dim3 pg((VOCAB + PBR - 1) / PBR, 2);
    pbuild_kernel<<<pg, 256>>>(E, Wx_f, b_f, Wx_b, b_b);
    lstm_kernel<<<128, 512>>>(inputs, Wh_f, Wh_b);
    logits_kernel<<<(BB * LL) / LB, 128>>>(Wd, bd);
    crf_kernel<<<BB / 4 + 1, 128>>>(labels, T, out, out_size);
}